// round 11
// baseline (speedup 1.0000x reference)
#include <cuda_runtime.h>

#define BB 8
#define CC 14
#define HH 512
#define WW 512
#define PP (HH * WW)          // 262144 = 2^18
#define KK 13                 // classes 1..13
#define NBK (BB * KK)         // 104
#define THREADS 256
#define WARPS_PER_IMG (PP / 32)                 // 8192
#define GRID_BLOCKS ((BB * PP) / THREADS)       // 8192 (2 threads per px-pair)
#define CHALF 7               // channels per lane half
#define DEPTH 3               // software-pipeline depth (channels prefetched)

// Global scratch. Zero-initialized at module load; the last block resets
// them after consuming, so every invocation starts from zeros.
__device__ float        g_kl[NBK];
__device__ unsigned int g_n[NBK];
__device__ unsigned int g_flag[NBK];
__device__ unsigned int g_count;

__global__ void __launch_bounds__(THREADS, 8) bkd_fused_kernel(
    const float* __restrict__ S,
    const float* __restrict__ T,
    const int*   __restrict__ gt,
    float*       __restrict__ out)
{
    __shared__ float        s_kl[KK];
    __shared__ unsigned int s_n[KK];
    __shared__ unsigned int s_flag[KK];
    __shared__ unsigned int s_isLast;
    if (threadIdx.x < KK) {
        s_kl[threadIdx.x]   = 0.0f;
        s_n[threadIdx.x]    = 0u;
        s_flag[threadIdx.x] = 0u;
    }
    __syncthreads();

    // Each warp owns 32 consecutive pixels of one image.
    // lanes 0..15  : channels 0..6   of pixel pair (2*pg, 2*pg+1)
    // lanes 16..31 : channels 7..13  of the same pixel pair
    const int tid     = blockIdx.x * blockDim.x + threadIdx.x;
    const int warp_g  = tid >> 5;
    const int lane    = threadIdx.x & 31;
    const int pg      = lane & 15;
    const int ch_half = lane >> 4;

    const int b       = warp_g >> 13;             // / WARPS_PER_IMG
    const int hw      = ((warp_g & (WARPS_PER_IMG - 1)) << 5) + (pg << 1);
    const int h       = hw >> 9;
    const int w       = hw & 511;
    const int cbase   = ch_half * CHALF;

    const float* Sp = S + ((size_t)b * CC + cbase) * PP + hw;
    const float* Tp = T + ((size_t)b * CC + cbase) * PP + hw;

    // ---- prime the pipeline: issue first DEPTH channels of loads ----
    float2 bs[DEPTH], bt[DEPTH];
#pragma unroll
    for (int i = 0; i < DEPTH; i++) {
        bs[i] = __ldcs((const float2*)(Sp + (size_t)i * PP));
        bt[i] = __ldcs((const float2*)(Tp + (size_t)i * PP));
    }

    // ---- boundary detection on lanes 0..15 only (overlaps load flight) ----
    bool bnd0 = false, bnd1 = false;
    int2 gc = make_int2(0, 0);
    if (ch_half == 0) {
        const int* gtb = gt + (size_t)b * PP;
        gc = *(const int2*)(gtb + hw);
        int2 gu = (h > 0)      ? *(const int2*)(gtb + hw - WW) : make_int2(-1, -1);
        int2 gd = (h < HH - 1) ? *(const int2*)(gtb + hw + WW) : make_int2(-1, -1);
        int gl = (w > 0)       ? gtb[hw - 1] : -1;
        int gr = (w + 2 < WW)  ? gtb[hw + 2] : -1;

        bnd0 = (gc.x >= 1) &&
               (gu.x != gc.x || gd.x != gc.x || gl   != gc.x || gc.y != gc.x);
        bnd1 = (gc.y >= 1) &&
               (gu.y != gc.y || gd.y != gc.y || gc.x != gc.y || gr   != gc.y);
    }

    // ---- pipelined partial softmax/KL accumulation over 7 channels ----
    float ZS0 = 0.f, ZS1 = 0.f;
    float ZT0 = 0.f, ZT1 = 0.f;
    float A0  = 0.f, A1  = 0.f;

#pragma unroll
    for (int c = 0; c < CHALF; c++) {
        const int slot = c % DEPTH;           // constant after full unroll
        float2 xs = bs[slot];
        float2 xt = bt[slot];
        if (c + DEPTH < CHALF) {              // issue next loads BEFORE compute
            bs[slot] = __ldcs((const float2*)(Sp + (size_t)(c + DEPTH) * PP));
            bt[slot] = __ldcs((const float2*)(Tp + (size_t)(c + DEPTH) * PP));
        }
        float es0 = __expf(xs.x), et0 = __expf(xt.x);
        float es1 = __expf(xs.y), et1 = __expf(xt.y);
        ZS0 += es0; ZT0 += et0; A0 = fmaf(et0, xt.x - xs.x, A0);
        ZS1 += es1; ZT1 += et1; A1 = fmaf(et1, xt.y - xs.y, A1);
    }

    // ---- combine channel halves: lane L gets lane L+16's partials ----
    ZS0 += __shfl_down_sync(0xffffffffu, ZS0, 16);
    ZT0 += __shfl_down_sync(0xffffffffu, ZT0, 16);
    A0  += __shfl_down_sync(0xffffffffu, A0,  16);
    ZS1 += __shfl_down_sync(0xffffffffu, ZS1, 16);
    ZT1 += __shfl_down_sync(0xffffffffu, ZT1, 16);
    A1  += __shfl_down_sync(0xffffffffu, A1,  16);

    // ---- per-block shared accumulation (lanes 0..15 hold full sums) ----
    if (bnd0) {
        float r  = __fdividef(1.0f, ZT0);
        float kl = A0 * r + __logf(ZS0 * r);
        int k = gc.x - 1;
        atomicAdd(&s_kl[k], kl);
        atomicAdd(&s_n[k], 1u);
        if (hw > 0) s_flag[k] = 1u;           // idempotent racing write
    }
    if (bnd1) {
        float r  = __fdividef(1.0f, ZT1);
        float kl = A1 * r + __logf(ZS1 * r);
        int k = gc.y - 1;
        atomicAdd(&s_kl[k], kl);
        atomicAdd(&s_n[k], 1u);
        s_flag[k] = 1u;                        // hw+1 > 0 always
    }
    __syncthreads();

    if (threadIdx.x < KK) {
        int k   = threadIdx.x;
        int idx = b * KK + k;
        if (s_n[k] > 0u) {
            atomicAdd(&g_kl[idx], s_kl[k]);
            atomicAdd(&g_n[idx],  s_n[k]);
        }
        if (s_flag[k]) atomicOr(&g_flag[idx], 1u);
    }

    // ---- last-block-done finalize (fused reduction + scratch reset) ----
    __threadfence();
    if (threadIdx.x == 0) {
        unsigned int v = atomicAdd(&g_count, 1u);
        s_isLast = (v == (unsigned int)(GRID_BLOCKS - 1)) ? 1u : 0u;
    }
    __syncthreads();

    if (s_isLast) {
        __shared__ float sred[256];
        int i = threadIdx.x;
        float t = 0.0f;
        if (i < NBK && g_flag[i]) {
            unsigned int n = g_n[i];
            if (n < 1u) n = 1u;
            t = g_kl[i] / (14.0f * (float)n);
        }
        sred[i] = t;
        __syncthreads();
#pragma unroll
        for (int s = 128; s > 0; s >>= 1) {
            if (i < s) sred[i] += sred[i + s];
            __syncthreads();
        }
        if (i == 0) {
            out[0] = sred[0];        // LOSS_WEIGHT * TAU^2 == 1
            g_count = 0u;            // reset for next replay
        }
        if (i < NBK) {
            g_kl[i]   = 0.0f;
            g_n[i]    = 0u;
            g_flag[i] = 0u;
        }
    }
}

extern "C" void kernel_launch(void* const* d_in, const int* in_sizes, int n_in,
                              void* d_out, int out_size) {
    const float* S  = (const float*)d_in[0];
    const float* T  = (const float*)d_in[1];
    const int*   gt = (const int*)d_in[2];
    float* out = (float*)d_out;

    bkd_fused_kernel<<<GRID_BLOCKS, THREADS>>>(S, T, gt, out);
}

// round 12
// speedup vs baseline: 1.1140x; 1.1140x over previous
#include <cuda_runtime.h>

#define BB 8
#define CC 14
#define HH 512
#define WW 512
#define PP (HH * WW)          // 262144 = 2^18
#define KK 13                 // classes 1..13
#define NBK (BB * KK)         // 104
#define THREADS 256
#define UNITS ((BB * PP / 2) / THREADS)   // 4096 work units (512 px each)
#define GRID_BLOCKS (152 * 7)             // 1064: one wave, 7 blocks/SM
#define DEPTH 3               // software-pipeline depth (channels prefetched)

// Global scratch. Zero-initialized at module load; the last block resets
// them after consuming, so every invocation starts from zeros.
__device__ float        g_kl[NBK];
__device__ unsigned int g_n[NBK];
__device__ unsigned int g_flag[NBK];
__device__ unsigned int g_count;

__global__ void __launch_bounds__(THREADS, 7) bkd_fused_kernel(
    const float* __restrict__ S,
    const float* __restrict__ T,
    const int*   __restrict__ gt,
    float*       __restrict__ out)
{
    __shared__ float        s_kl[KK];
    __shared__ unsigned int s_n[KK];
    __shared__ unsigned int s_flag[KK];
    __shared__ unsigned int s_isLast;

    // ---- grid-stride over work units; all blocks resident in one wave ----
    for (int u = blockIdx.x; u < UNITS; u += GRID_BLOCKS) {
        // zero the per-unit class bins (previous unit's flush completed
        // before the loop-top sync below)
        if (threadIdx.x < KK) {
            s_kl[threadIdx.x]   = 0.0f;
            s_n[threadIdx.x]    = 0u;
            s_flag[threadIdx.x] = 0u;
        }
        __syncthreads();

        const int p0  = (u * THREADS + threadIdx.x) << 1;   // 2 px per thread
        const int b   = p0 >> 18;                // / PP
        const int hw  = p0 & (PP - 1);
        const int h   = hw >> 9;                 // / 512
        const int w   = hw & 511;

        const float* Sp = S + (size_t)b * CC * PP + hw;
        const float* Tp = T + (size_t)b * CC * PP + hw;

        // ---- prime the pipeline: first DEPTH channels ----
        float2 bs[DEPTH], bt[DEPTH];
#pragma unroll
        for (int i = 0; i < DEPTH; i++) {
            bs[i] = __ldcs((const float2*)(Sp + (size_t)i * PP));
            bt[i] = __ldcs((const float2*)(Tp + (size_t)i * PP));
        }

        // ---- boundary detection (overlaps with in-flight S/T loads) ----
        const int* gtb = gt + (size_t)b * PP;
        int2 gc = *(const int2*)(gtb + hw);
        int2 gu = (h > 0)      ? *(const int2*)(gtb + hw - WW) : make_int2(-1, -1);
        int2 gd = (h < HH - 1) ? *(const int2*)(gtb + hw + WW) : make_int2(-1, -1);
        int gl = (w > 0)       ? gtb[hw - 1] : -1;
        int gr = (w + 2 < WW)  ? gtb[hw + 2] : -1;

        const bool bnd0 = (gc.x >= 1) &&
                          (gu.x != gc.x || gd.x != gc.x || gl   != gc.x || gc.y != gc.x);
        const bool bnd1 = (gc.y >= 1) &&
                          (gu.y != gc.y || gd.y != gc.y || gc.x != gc.y || gr   != gc.y);

        // ---- pipelined single-pass softmax/KL accumulation ----
        // kl = A/Z_T + log(Z_S/Z_T)
        float ZS0 = 0.f, ZS1 = 0.f;
        float ZT0 = 0.f, ZT1 = 0.f;
        float A0  = 0.f, A1  = 0.f;

#pragma unroll
        for (int c = 0; c < CC; c++) {
            const int slot = c % DEPTH;           // constant after full unroll
            float2 xs = bs[slot];
            float2 xt = bt[slot];
            if (c + DEPTH < CC) {                 // issue next loads BEFORE compute
                bs[slot] = __ldcs((const float2*)(Sp + (size_t)(c + DEPTH) * PP));
                bt[slot] = __ldcs((const float2*)(Tp + (size_t)(c + DEPTH) * PP));
            }
            float es0 = __expf(xs.x), et0 = __expf(xt.x);
            float es1 = __expf(xs.y), et1 = __expf(xt.y);
            ZS0 += es0; ZT0 += et0; A0 = fmaf(et0, xt.x - xs.x, A0);
            ZS1 += es1; ZT1 += et1; A1 = fmaf(et1, xt.y - xs.y, A1);
        }

        // ---- per-unit shared accumulation into 13 class bins ----
        if (bnd0) {
            float r  = __fdividef(1.0f, ZT0);
            float kl = A0 * r + __logf(ZS0 * r);
            int k = gc.x - 1;
            atomicAdd(&s_kl[k], kl);
            atomicAdd(&s_n[k], 1u);
            if (hw > 0) s_flag[k] = 1u;           // idempotent racing write
        }
        if (bnd1) {
            float r  = __fdividef(1.0f, ZT1);
            float kl = A1 * r + __logf(ZS1 * r);
            int k = gc.y - 1;
            atomicAdd(&s_kl[k], kl);
            atomicAdd(&s_n[k], 1u);
            s_flag[k] = 1u;                        // hw+1 > 0 always
        }
        __syncthreads();

        // flush unit bins to global [b,k] accumulators
        if (threadIdx.x < KK) {
            int k   = threadIdx.x;
            int idx = b * KK + k;
            if (s_n[k] > 0u) {
                atomicAdd(&g_kl[idx], s_kl[k]);
                atomicAdd(&g_n[idx],  s_n[k]);
            }
            if (s_flag[k]) atomicOr(&g_flag[idx], 1u);
        }
        __syncthreads();   // flush complete before next unit re-zeros bins
    }

    // ---- last-block-done finalize (fused reduction + scratch reset) ----
    __threadfence();
    if (threadIdx.x == 0) {
        unsigned int v = atomicAdd(&g_count, 1u);
        s_isLast = (v == (unsigned int)(GRID_BLOCKS - 1)) ? 1u : 0u;
    }
    __syncthreads();

    if (s_isLast) {
        __shared__ float sred[256];
        int i = threadIdx.x;
        float t = 0.0f;
        if (i < NBK && g_flag[i]) {
            unsigned int n = g_n[i];
            if (n < 1u) n = 1u;
            t = g_kl[i] / (14.0f * (float)n);
        }
        sred[i] = t;
        __syncthreads();
#pragma unroll
        for (int s = 128; s > 0; s >>= 1) {
            if (i < s) sred[i] += sred[i + s];
            __syncthreads();
        }
        if (i == 0) {
            out[0] = sred[0];        // LOSS_WEIGHT * TAU^2 == 1
            g_count = 0u;            // reset for next replay
        }
        if (i < NBK) {
            g_kl[i]   = 0.0f;
            g_n[i]    = 0u;
            g_flag[i] = 0u;
        }
    }
}

extern "C" void kernel_launch(void* const* d_in, const int* in_sizes, int n_in,
                              void* d_out, int out_size) {
    const float* S  = (const float*)d_in[0];
    const float* T  = (const float*)d_in[1];
    const int*   gt = (const int*)d_in[2];
    float* out = (float*)d_out;

    bkd_fused_kernel<<<GRID_BLOCKS, THREADS>>>(S, T, gt, out);
}

// round 13
// speedup vs baseline: 1.1235x; 1.0085x over previous
#include <cuda_runtime.h>

#define BB 8
#define CC 14
#define HH 512
#define WW 512
#define PP (HH * WW)          // 262144 = 2^18
#define KK 13                 // classes 1..13
#define NBK (BB * KK)         // 104
#define THREADS 256
#define UNITS ((BB * PP / 2) / THREADS)   // 4096 work units (512 px each)
#define GRID_BLOCKS (152 * 7)             // 1064: one wave, 7 blocks/SM
#define DEPTH 3               // software-pipeline depth (channels prefetched)

// Global scratch. Zero-initialized at module load; the last block resets
// them after consuming, so every invocation starts from zeros.
__device__ float        g_kl[NBK];
__device__ unsigned int g_n[NBK];
__device__ unsigned int g_flag[NBK];
__device__ unsigned int g_count;

__global__ void __launch_bounds__(THREADS, 7) bkd_fused_kernel(
    const float* __restrict__ S,
    const float* __restrict__ T,
    const int*   __restrict__ gt,
    float*       __restrict__ out)
{
    // Per-block accumulators over ALL (b,k) bins — zeroed once, flushed once.
    __shared__ float        s_kl[NBK];
    __shared__ unsigned int s_n[NBK];
    __shared__ unsigned int s_flag[NBK];
    __shared__ unsigned int s_isLast;

    if (threadIdx.x < NBK) {
        s_kl[threadIdx.x]   = 0.0f;
        s_n[threadIdx.x]    = 0u;
        s_flag[threadIdx.x] = 0u;
    }
    __syncthreads();   // the ONLY barrier before the final flush

    // ---- barrier-free grid-stride unit loop (one resident wave) ----
    for (int u = blockIdx.x; u < UNITS; u += GRID_BLOCKS) {
        const int p0  = (u * THREADS + threadIdx.x) << 1;   // 2 px per thread
        const int b   = p0 >> 18;                // / PP
        const int hw  = p0 & (PP - 1);
        const int h   = hw >> 9;                 // / 512
        const int w   = hw & 511;

        const float* Sp = S + (size_t)b * CC * PP + hw;
        const float* Tp = T + (size_t)b * CC * PP + hw;

        // ---- prime the pipeline: first DEPTH channels ----
        float2 bs[DEPTH], bt[DEPTH];
#pragma unroll
        for (int i = 0; i < DEPTH; i++) {
            bs[i] = __ldcs((const float2*)(Sp + (size_t)i * PP));
            bt[i] = __ldcs((const float2*)(Tp + (size_t)i * PP));
        }

        // ---- boundary detection (overlaps with in-flight S/T loads) ----
        const int* gtb = gt + (size_t)b * PP;
        int2 gc = *(const int2*)(gtb + hw);
        int2 gu = (h > 0)      ? *(const int2*)(gtb + hw - WW) : make_int2(-1, -1);
        int2 gd = (h < HH - 1) ? *(const int2*)(gtb + hw + WW) : make_int2(-1, -1);
        int gl = (w > 0)       ? gtb[hw - 1] : -1;
        int gr = (w + 2 < WW)  ? gtb[hw + 2] : -1;

        const bool bnd0 = (gc.x >= 1) &&
                          (gu.x != gc.x || gd.x != gc.x || gl   != gc.x || gc.y != gc.x);
        const bool bnd1 = (gc.y >= 1) &&
                          (gu.y != gc.y || gd.y != gc.y || gc.x != gc.y || gr   != gc.y);

        // ---- pipelined single-pass softmax/KL accumulation ----
        // kl = A/Z_T + log(Z_S/Z_T)
        float ZS0 = 0.f, ZS1 = 0.f;
        float ZT0 = 0.f, ZT1 = 0.f;
        float A0  = 0.f, A1  = 0.f;

#pragma unroll
        for (int c = 0; c < CC; c++) {
            const int slot = c % DEPTH;           // constant after full unroll
            float2 xs = bs[slot];
            float2 xt = bt[slot];
            if (c + DEPTH < CC) {                 // issue next loads BEFORE compute
                bs[slot] = __ldcs((const float2*)(Sp + (size_t)(c + DEPTH) * PP));
                bt[slot] = __ldcs((const float2*)(Tp + (size_t)(c + DEPTH) * PP));
            }
            float es0 = __expf(xs.x), et0 = __expf(xt.x);
            float es1 = __expf(xs.y), et1 = __expf(xt.y);
            ZS0 += es0; ZT0 += et0; A0 = fmaf(et0, xt.x - xs.x, A0);
            ZS1 += es1; ZT1 += et1; A1 = fmaf(et1, xt.y - xs.y, A1);
        }

        // ---- accumulate into per-block [b,k] bins (no barriers) ----
        if (bnd0) {
            float r  = __fdividef(1.0f, ZT0);
            float kl = A0 * r + __logf(ZS0 * r);
            int idx = b * KK + (gc.x - 1);
            atomicAdd(&s_kl[idx], kl);
            atomicAdd(&s_n[idx], 1u);
            if (hw > 0) s_flag[idx] = 1u;         // idempotent racing write
        }
        if (bnd1) {
            float r  = __fdividef(1.0f, ZT1);
            float kl = A1 * r + __logf(ZS1 * r);
            int idx = b * KK + (gc.y - 1);
            atomicAdd(&s_kl[idx], kl);
            atomicAdd(&s_n[idx], 1u);
            s_flag[idx] = 1u;                     // hw+1 > 0 always
        }
    }

    // ---- single flush of per-block bins to global accumulators ----
    __syncthreads();
    if (threadIdx.x < NBK) {
        int idx = threadIdx.x;
        if (s_n[idx] > 0u) {
            atomicAdd(&g_kl[idx], s_kl[idx]);
            atomicAdd(&g_n[idx],  s_n[idx]);
        }
        if (s_flag[idx]) atomicOr(&g_flag[idx], 1u);
    }

    // ---- last-block-done finalize (fused reduction + scratch reset) ----
    __threadfence();
    if (threadIdx.x == 0) {
        unsigned int v = atomicAdd(&g_count, 1u);
        s_isLast = (v == (unsigned int)(GRID_BLOCKS - 1)) ? 1u : 0u;
    }
    __syncthreads();

    if (s_isLast) {
        __shared__ float sred[256];
        int i = threadIdx.x;
        float t = 0.0f;
        if (i < NBK && g_flag[i]) {
            unsigned int n = g_n[i];
            if (n < 1u) n = 1u;
            t = g_kl[i] / (14.0f * (float)n);
        }
        sred[i] = t;
        __syncthreads();
#pragma unroll
        for (int s = 128; s > 0; s >>= 1) {
            if (i < s) sred[i] += sred[i + s];
            __syncthreads();
        }
        if (i == 0) {
            out[0] = sred[0];        // LOSS_WEIGHT * TAU^2 == 1
            g_count = 0u;            // reset for next replay
        }
        if (i < NBK) {
            g_kl[i]   = 0.0f;
            g_n[i]    = 0u;
            g_flag[i] = 0u;
        }
    }
}

extern "C" void kernel_launch(void* const* d_in, const int* in_sizes, int n_in,
                              void* d_out, int out_size) {
    const float* S  = (const float*)d_in[0];
    const float* T  = (const float*)d_in[1];
    const int*   gt = (const int*)d_in[2];
    float* out = (float*)d_out;

    bkd_fused_kernel<<<GRID_BLOCKS, THREADS>>>(S, T, gt, out);
}